// round 16
// baseline (speedup 1.0000x reference)
#include <cuda_runtime.h>
#include <cuda_bf16.h>
#include <math.h>
#include <stdint.h>

#define NN 50000
#define EE 800000
#define HC 128
#define BB 64
#define OUTC 16
#define NB 196   // (NN+255)/256

// ---------------- scratch (device globals; no allocation allowed) ----------
__device__ float g_qn[NN * HC];
__device__ __nv_bfloat16 g_knb[NN * HC];
__device__ __nv_bfloat16 g_vnb[NN * HC];
__device__ float g_sk[NN * HC];
__device__ float g_U [NN * HC];
__device__ float g_h1[NN * HC];
__device__ float g_h2[NN * HC];
__device__ int   g_deg[NN];
__device__ int   g_off[NN + 1];
__device__ int   g_cur[NN];
__device__ int   g_bsum[NB];
__device__ int   g_boff[NB];
__device__ int   g_psrc[EE];
__device__ int   g_peid[EE];
__device__ float g_pool[BB * HC];
__device__ int   g_bnd[BB + 1];
__device__ float g_zero[128];    // stays zero (zero-initialized, never written)
// pre-split transposed weights: [10 matrices][n(128)][k(128)] bf16 hi/lo
// m 0..3: layer1 q/k/v/s, 4..7: layer2, 8: Bu(we1), 9: Bu(we2)
__device__ __nv_bfloat16 g_wth[10 * 128 * 128];
__device__ __nv_bfloat16 g_wtl[10 * 128 * 128];

// ---------------- helpers ----------------------------------------------------
__device__ __forceinline__ uint32_t smem_u32(const void* p) {
    uint32_t a;
    asm("{ .reg .u64 t; cvta.to.shared.u64 t, %1; cvt.u32.u64 %0, t; }" : "=r"(a) : "l"(p));
    return a;
}
__device__ __forceinline__ void ldsm4(uint32_t* r, uint32_t addr) {
    asm volatile("ldmatrix.sync.aligned.m8n8.x4.shared.b16 {%0,%1,%2,%3}, [%4];"
        : "=r"(r[0]), "=r"(r[1]), "=r"(r[2]), "=r"(r[3]) : "r"(addr));
}
__device__ __forceinline__ void mma_bf16(float* d, const uint32_t* a, const uint32_t* b) {
    asm volatile(
        "mma.sync.aligned.m16n8k16.row.col.f32.bf16.bf16.f32 "
        "{%0,%1,%2,%3}, {%4,%5,%6,%7}, {%8,%9}, {%0,%1,%2,%3};"
        : "+f"(d[0]), "+f"(d[1]), "+f"(d[2]), "+f"(d[3])
        : "r"(a[0]), "r"(a[1]), "r"(a[2]), "r"(a[3]), "r"(b[0]), "r"(b[1]));
}
// streaming 128-bit load: LDG.E.CS.128
__device__ __forceinline__ float4 ldg_cs(const float* p) {
    return __ldcs(reinterpret_cast<const float4*>(p));
}
// bf16x4 gather -> fp32 (kn/vn)
__device__ __forceinline__ float4 ldg_bf4(const __nv_bfloat16* p) {
    const uint2 r = __ldg(reinterpret_cast<const uint2*>(p));
    const __nv_bfloat162 b0 = *reinterpret_cast<const __nv_bfloat162*>(&r.x);
    const __nv_bfloat162 b1 = *reinterpret_cast<const __nv_bfloat162*>(&r.y);
    const float2 f0 = __bfloat1622float2(b0);
    const float2 f1 = __bfloat1622float2(b1);
    return make_float4(f0.x, f0.y, f1.x, f1.y);
}

// ---------------- setup: weight split/transpose + zero deg ------------------
struct WArgs { const float* w[10]; };

__global__ void setup_kernel(WArgs a) {
    const int m = blockIdx.y;
    const float* __restrict__ W = a.w[m];
    int i = blockIdx.x * 256 + threadIdx.x;   // 0..16383
    int n = i >> 7, k = i & 127;
    float v;
    if (m < 8) {
        v = W[k * 128 + n];                   // transpose of [128,128]
    } else {
        // Bu[k][n] for we [32,128]: block-diagonal per head
        v = ((n >> 5) == (k >> 5)) ? W[(n & 31) * 128 + k] : 0.f;
    }
    __nv_bfloat16 hi = __float2bfloat16(v);
    float lof = v - __bfloat162float(hi);
    g_wth[m * 16384 + n * 128 + k] = hi;
    g_wtl[m * 16384 + n * 128 + k] = __float2bfloat16(lof);

    // fused zeroing (linear gid over the full 640-block grid)
    int gid = (blockIdx.y * 64 + blockIdx.x) * 256 + threadIdx.x;
    if (gid < NN) g_deg[gid] = 0;
}

__global__ void hist_kernel(const int* __restrict__ tgt) {
    int e = blockIdx.x * 256 + threadIdx.x;
    if (e < EE) atomicAdd(&g_deg[tgt[e]], 1);
}

// phase 1: per-block local exclusive scan + block totals
__global__ __launch_bounds__(256) void scan1_kernel() {
    __shared__ int sh[256];
    const int t = threadIdx.x;
    const int i = blockIdx.x * 256 + t;
    int v = (i < NN) ? g_deg[i] : 0;
    sh[t] = v;
    __syncthreads();
#pragma unroll
    for (int off = 1; off < 256; off <<= 1) {
        int x = (t >= off) ? sh[t - off] : 0;
        __syncthreads();
        sh[t] += x;
        __syncthreads();
    }
    if (i < NN) g_off[i] = sh[t] - v;     // local exclusive
    if (t == 255) g_bsum[blockIdx.x] = sh[255];
}

// phase 2: scan of block totals (single small block)
__global__ __launch_bounds__(256) void scan2_kernel() {
    __shared__ int sh[256];
    const int t = threadIdx.x;
    int v = (t < NB) ? g_bsum[t] : 0;
    sh[t] = v;
    __syncthreads();
#pragma unroll
    for (int off = 1; off < 256; off <<= 1) {
        int x = (t >= off) ? sh[t - off] : 0;
        __syncthreads();
        sh[t] += x;
        __syncthreads();
    }
    if (t < NB) g_boff[t] = sh[t] - v;    // exclusive
    if (t == NB - 1) g_off[NN] = sh[t];
}

// phase 3: add block offsets, init cursors
__global__ __launch_bounds__(256) void scan3_kernel() {
    const int i = blockIdx.x * 256 + threadIdx.x;
    if (i < NN) {
        int o = g_off[i] + g_boff[i >> 8];
        g_off[i] = o;
        g_cur[i] = o;
    }
}

__global__ void scatter_kernel(const int* __restrict__ src, const int* __restrict__ tgt) {
    int e = blockIdx.x * 256 + threadIdx.x;
    if (e < EE) {
        int p = atomicAdd(&g_cur[tgt[e]], 1);
        g_psrc[p] = src[e];
        g_peid[p] = e;
    }
}

// ---------------- HMMA node GEMM + fused U pass ------------------------------
// persistent CTAs (grid=152, internal tile loop), 512 threads, 4x4 warp tiling.
// z=0: qn fp32 + smem hi/lo cache; z=1: kn bf16 (2-term); z=2: vn bf16 (2-term);
// z=3: sk fp32; z=4: U = qn @ Bu (block-diagonal, 2 ksteps/warp).
struct G5 {
    const float* bias[5];
    void*        out[5];
    int          wbase;   // 0 for layer1, 4 for layer2
};

#define ROWB   272
#define OFF_AH 0
#define OFF_AL (128 * ROWB)
#define OFF_BH (2 * 128 * ROWB)
#define OFF_BL (3 * 128 * ROWB)
#define OFF_QH (4 * 128 * ROWB)
#define OFF_QL (5 * 128 * ROWB)
#define SMTOT  (6 * 128 * ROWB)

__global__ __launch_bounds__(512, 1) void node_gemm_mma(const float* __restrict__ A, G5 g, int M)
{
    extern __shared__ char sm[];
    const uint32_t sb = smem_u32(sm);
    const int tid  = threadIdx.x;
    const int wid  = tid >> 5;
    const int lane = tid & 31;
    const int wid_n = wid & 3;     // 32-col strip
    const int wid_m = wid >> 2;    // 32-row strip

    // fragment addresses
    const uint32_t a_base = sb + (uint32_t)((wid_m * 32 + (lane & 15)) * ROWB + (lane >> 4) * 16);
    const uint32_t b4_base = sb + (uint32_t)(((lane & 7) + ((lane >> 4) << 3)) * ROWB
                                             + (((lane >> 3) & 1) << 4));
    const int r0l = wid_m * 32 + (lane >> 2);   // local row of acc[0][.][0/1]
    const int cb  = (lane & 3) * 2;

    const int ntiles = (M + 127) / 128;
    for (int tile = blockIdx.x; tile < ntiles; tile += gridDim.x) {
        const int m0 = tile * 128;
        __syncthreads();   // prior tile fully consumed before A overwrite

        // --- convert A tile (128x128 fp32) to bf16 hi/lo in padded smem ---
        for (int idx = tid; idx < 128 * 32; idx += 512) {
            int r  = idx >> 5;
            int kc = (idx & 31) * 4;
            int grow = m0 + r;
            float4 v = make_float4(0.f, 0.f, 0.f, 0.f);
            if (grow < M) v = *reinterpret_cast<const float4*>(A + (size_t)grow * 128 + kc);
            __nv_bfloat16 h0 = __float2bfloat16(v.x), h1 = __float2bfloat16(v.y);
            __nv_bfloat16 h2 = __float2bfloat16(v.z), h3 = __float2bfloat16(v.w);
            __nv_bfloat16 l0 = __float2bfloat16(v.x - __bfloat162float(h0));
            __nv_bfloat16 l1 = __float2bfloat16(v.y - __bfloat162float(h1));
            __nv_bfloat16 l2 = __float2bfloat16(v.z - __bfloat162float(h2));
            __nv_bfloat16 l3 = __float2bfloat16(v.w - __bfloat162float(h3));
            ushort4 hp = make_ushort4(__bfloat16_as_ushort(h0), __bfloat16_as_ushort(h1),
                                      __bfloat16_as_ushort(h2), __bfloat16_as_ushort(h3));
            ushort4 lp = make_ushort4(__bfloat16_as_ushort(l0), __bfloat16_as_ushort(l1),
                                      __bfloat16_as_ushort(l2), __bfloat16_as_ushort(l3));
            *reinterpret_cast<ushort4*>(sm + OFF_AH + r * ROWB + kc * 2) = hp;
            *reinterpret_cast<ushort4*>(sm + OFF_AL + r * ROWB + kc * 2) = lp;
        }

        float acc[2][4][4];

        for (int z = 0; z < 5; ++z) {
            __syncthreads();   // previous B reads done; z=0 Aq writes visible for z=4
            const int wsel = (z < 4) ? (g.wbase + z) : (8 + (g.wbase >> 2));
            const __nv_bfloat16* shp = g_wth + (size_t)wsel * 16384;
            const __nv_bfloat16* slp = g_wtl + (size_t)wsel * 16384;
            for (int idx = tid; idx < 128 * 16; idx += 512) {
                int r = idx >> 4, s = idx & 15;
                *reinterpret_cast<uint4*>(sm + OFF_BH + r * ROWB + s * 16) =
                    *reinterpret_cast<const uint4*>(shp + r * 128 + s * 8);
                *reinterpret_cast<uint4*>(sm + OFF_BL + r * ROWB + s * 16) =
                    *reinterpret_cast<const uint4*>(slp + r * 128 + s * 8);
            }
            __syncthreads();

            const uint32_t ahof = (z == 4) ? OFF_QH : OFF_AH;
            const uint32_t alof = (z == 4) ? OFF_QL : OFF_AL;

#pragma unroll
            for (int mt = 0; mt < 2; ++mt)
#pragma unroll
                for (int nt = 0; nt < 4; ++nt)
#pragma unroll
                    for (int q = 0; q < 4; ++q) acc[mt][nt][q] = 0.f;

            if (z == 1 || z == 2) {
                // 2-term split (output truncated to bf16 anyway): ah*bh + ah*bl
#pragma unroll 2
                for (int ki = 0; ki < 8; ++ki) {
                    const uint32_t ko = (uint32_t)(ki * 32);
                    uint32_t ah[2][4], bh[2][4], bl[2][4];
#pragma unroll
                    for (int mt = 0; mt < 2; ++mt)
                        ldsm4(ah[mt], a_base + (uint32_t)(mt * 16 * ROWB) + OFF_AH + ko);
#pragma unroll
                    for (int np = 0; np < 2; ++np) {
                        const uint32_t bo = (uint32_t)((wid_n * 32 + np * 16) * ROWB) + ko;
                        ldsm4(bh[np], b4_base + OFF_BH + bo);
                        ldsm4(bl[np], b4_base + OFF_BL + bo);
                    }
#pragma unroll
                    for (int mt = 0; mt < 2; ++mt)
#pragma unroll
                        for (int np = 0; np < 2; ++np) {
                            mma_bf16(acc[mt][np * 2],     ah[mt], bh[np]);
                            mma_bf16(acc[mt][np * 2],     ah[mt], bl[np]);
                            mma_bf16(acc[mt][np * 2 + 1], ah[mt], bh[np] + 2);
                            mma_bf16(acc[mt][np * 2 + 1], ah[mt], bl[np] + 2);
                        }
                }
            } else {
                const int ks0 = (z == 4) ? (wid_n * 2) : 0;
                const int ksN = (z == 4) ? 2 : 8;
#pragma unroll 2
                for (int ki = 0; ki < ksN; ++ki) {
                    const uint32_t ko = (uint32_t)((ks0 + ki) * 32);
                    uint32_t ah[2][4], al[2][4], bh[2][4], bl[2][4];
#pragma unroll
                    for (int mt = 0; mt < 2; ++mt) {
                        ldsm4(ah[mt], a_base + (uint32_t)(mt * 16 * ROWB) + ahof + ko);
                        ldsm4(al[mt], a_base + (uint32_t)(mt * 16 * ROWB) + alof + ko);
                    }
#pragma unroll
                    for (int np = 0; np < 2; ++np) {
                        const uint32_t bo = (uint32_t)((wid_n * 32 + np * 16) * ROWB) + ko;
                        ldsm4(bh[np], b4_base + OFF_BH + bo);
                        ldsm4(bl[np], b4_base + OFF_BL + bo);
                    }
#pragma unroll
                    for (int mt = 0; mt < 2; ++mt)
#pragma unroll
                        for (int np = 0; np < 2; ++np) {
                            mma_bf16(acc[mt][np * 2],     ah[mt], bh[np]);
                            mma_bf16(acc[mt][np * 2],     ah[mt], bl[np]);
                            mma_bf16(acc[mt][np * 2],     al[mt], bh[np]);
                            mma_bf16(acc[mt][np * 2 + 1], ah[mt], bh[np] + 2);
                            mma_bf16(acc[mt][np * 2 + 1], ah[mt], bl[np] + 2);
                            mma_bf16(acc[mt][np * 2 + 1], al[mt], bh[np] + 2);
                        }
                }
            }

            // --- epilogue: bias add + store (z=1,2 -> bf16; else fp32; z=0 qn cache) ---
            const float* bias = g.bias[z];
            const bool is_bf = (z == 1 || z == 2);
            float* outf = (float*)g.out[z];
            __nv_bfloat16* outb = (__nv_bfloat16*)g.out[z];
#pragma unroll
            for (int mt = 0; mt < 2; ++mt) {
                const int rl0 = r0l + mt * 16;
                const int gr0 = m0 + rl0;
                const int gr1 = gr0 + 8;
#pragma unroll
                for (int nt = 0; nt < 4; ++nt) {
                    const int c = wid_n * 32 + nt * 8 + cb;
                    const float2 bv = *reinterpret_cast<const float2*>(bias + c);
                    float2 o0 = make_float2(acc[mt][nt][0] + bv.x, acc[mt][nt][1] + bv.y);
                    float2 o1 = make_float2(acc[mt][nt][2] + bv.x, acc[mt][nt][3] + bv.y);
                    if (is_bf) {
                        if (gr0 < M)
                            *reinterpret_cast<__nv_bfloat162*>(outb + (size_t)gr0 * 128 + c) =
                                __floats2bfloat162_rn(o0.x, o0.y);
                        if (gr1 < M)
                            *reinterpret_cast<__nv_bfloat162*>(outb + (size_t)gr1 * 128 + c) =
                                __floats2bfloat162_rn(o1.x, o1.y);
                    } else {
                        if (gr0 < M) *reinterpret_cast<float2*>(outf + (size_t)gr0 * 128 + c) = o0;
                        if (gr1 < M) *reinterpret_cast<float2*>(outf + (size_t)gr1 * 128 + c) = o1;
                    }
                    if (z == 0) {
                        __nv_bfloat16 h0 = __float2bfloat16(o0.x), h1 = __float2bfloat16(o0.y);
                        __nv_bfloat16 l0 = __float2bfloat16(o0.x - __bfloat162float(h0));
                        __nv_bfloat16 l1 = __float2bfloat16(o0.y - __bfloat162float(h1));
                        *reinterpret_cast<ushort2*>(sm + OFF_QH + rl0 * ROWB + c * 2) =
                            make_ushort2(__bfloat16_as_ushort(h0), __bfloat16_as_ushort(h1));
                        *reinterpret_cast<ushort2*>(sm + OFF_QL + rl0 * ROWB + c * 2) =
                            make_ushort2(__bfloat16_as_ushort(l0), __bfloat16_as_ushort(l1));
                        __nv_bfloat16 h2 = __float2bfloat16(o1.x), h3 = __float2bfloat16(o1.y);
                        __nv_bfloat16 l2 = __float2bfloat16(o1.x - __bfloat162float(h2));
                        __nv_bfloat16 l3 = __float2bfloat16(o1.y - __bfloat162float(h3));
                        *reinterpret_cast<ushort2*>(sm + OFF_QH + (rl0 + 8) * ROWB + c * 2) =
                            make_ushort2(__bfloat16_as_ushort(h2), __bfloat16_as_ushort(h3));
                        *reinterpret_cast<ushort2*>(sm + OFF_QL + (rl0 + 8) * ROWB + c * 2) =
                            make_ushort2(__bfloat16_as_ushort(l2), __bfloat16_as_ushort(l3));
                    }
                }
            }
        }
    }
}

// ---------------- fused edge attention: warp per target node -----------------
// lane layout: head h = lane>>3, dims d0 = (lane&7)*4 (float4 per lane)
// kn/vn in bf16 (half traffic); q/U/sk fp32; ea streamed .cs
__global__ __launch_bounds__(256) void edge_attn(const float* __restrict__ ea,
                                                 const float* __restrict__ we,
                                                 float* __restrict__ outp)
{
    __shared__ float we_sm[32 * 132];
    for (int i = threadIdx.x; i < 32 * 128; i += 256)
        we_sm[(i >> 7) * 132 + (i & 127)] = we[i];
    __syncthreads();

    const int lane = threadIdx.x & 31;
    const int n = blockIdx.x * 8 + (threadIdx.x >> 5);
    if (n >= NN) return;

    const int h   = lane >> 3;
    const int sub = lane & 7;
    const int d0  = h * 32 + sub * 4;

    const float4 q4 = ldg_cs(g_qn + (size_t)n * 128 + d0);
    const float4 u4 = ldg_cs(g_U  + (size_t)n * 128 + d0);
    float m = -1e30f, den = 0.f;
    float4 av = make_float4(0.f, 0.f, 0.f, 0.f);
    float4 tt = make_float4(0.f, 0.f, 0.f, 0.f);

    const int e0 = g_off[n], e1 = g_off[n + 1];
    const float RS = 0.17677669529663687f * 1.4426950408889634f;  // 1/sqrt(32) * log2(e)

    int e = e0;
    for (; e + 2 <= e1; e += 2) {
        const int sA = g_psrc[e],     sB = g_psrc[e + 1];
        const int iA = g_peid[e],     iB = g_peid[e + 1];
        const float4 eaA = ldg_cs(ea + (size_t)iA * 32 + sub * 4);
        const float4 eaB = ldg_cs(ea + (size_t)iB * 32 + sub * 4);
        const float4 kA  = ldg_bf4(g_knb + (size_t)sA * 128 + d0);
        const float4 kB  = ldg_bf4(g_knb + (size_t)sB * 128 + d0);
        const float4 vA  = ldg_bf4(g_vnb + (size_t)sA * 128 + d0);
        const float4 vB  = ldg_bf4(g_vnb + (size_t)sB * 128 + d0);

        float rA = q4.x * kA.x + q4.y * kA.y + q4.z * kA.z + q4.w * kA.w
                 + eaA.x * u4.x + eaA.y * u4.y + eaA.z * u4.z + eaA.w * u4.w;
        float rB = q4.x * kB.x + q4.y * kB.y + q4.z * kB.z + q4.w * kB.w
                 + eaB.x * u4.x + eaB.y * u4.y + eaB.z * u4.z + eaB.w * u4.w;
        rA += __shfl_xor_sync(0xffffffffu, rA, 1);
        rB += __shfl_xor_sync(0xffffffffu, rB, 1);
        rA += __shfl_xor_sync(0xffffffffu, rA, 2);
        rB += __shfl_xor_sync(0xffffffffu, rB, 2);
        rA += __shfl_xor_sync(0xffffffffu, rA, 4);
        rB += __shfl_xor_sync(0xffffffffu, rB, 4);

        {
            const float al = rA * RS;
            const float nm = fmaxf(m, al);
            const float cf = exp2f(m - nm);
            const float a  = exp2f(al - nm);
            den = den * cf + a;
            av.x = av.x * cf + a * vA.x;  av.y = av.y * cf + a * vA.y;
            av.z = av.z * cf + a * vA.z;  av.w = av.w * cf + a * vA.w;
            tt.x = tt.x * cf + a * eaA.x; tt.y = tt.y * cf + a * eaA.y;
            tt.z = tt.z * cf + a * eaA.z; tt.w = tt.w * cf + a * eaA.w;
            m = nm;
        }
        {
            const float al = rB * RS;
            const float nm = fmaxf(m, al);
            const float cf = exp2f(m - nm);
            const float a  = exp2f(al - nm);
            den = den * cf + a;
            av.x = av.x * cf + a * vB.x;  av.y = av.y * cf + a * vB.y;
            av.z = av.z * cf + a * vB.z;  av.w = av.w * cf + a * vB.w;
            tt.x = tt.x * cf + a * eaB.x; tt.y = tt.y * cf + a * eaB.y;
            tt.z = tt.z * cf + a * eaB.z; tt.w = tt.w * cf + a * eaB.w;
            m = nm;
        }
    }
    for (; e < e1; ++e) {
        const int src = g_psrc[e];
        const int eid = g_peid[e];
        const float4 ea4 = ldg_cs(ea + (size_t)eid * 32 + sub * 4);
        const float4 k4  = ldg_bf4(g_knb + (size_t)src * 128 + d0);
        float r = q4.x * k4.x + q4.y * k4.y + q4.z * k4.z + q4.w * k4.w
                + ea4.x * u4.x + ea4.y * u4.y + ea4.z * u4.z + ea4.w * u4.w;
        r += __shfl_xor_sync(0xffffffffu, r, 1);
        r += __shfl_xor_sync(0xffffffffu, r, 2);
        r += __shfl_xor_sync(0xffffffffu, r, 4);

        const float al = r * RS;
        const float nm = fmaxf(m, al);
        const float cf = exp2f(m - nm);
        const float a  = exp2f(al - nm);
        den = den * cf + a;
        const float4 v4 = ldg_bf4(g_vnb + (size_t)src * 128 + d0);
        av.x = av.x * cf + a * v4.x;  av.y = av.y * cf + a * v4.y;
        av.z = av.z * cf + a * v4.z;  av.w = av.w * cf + a * v4.w;
        tt.x = tt.x * cf + a * ea4.x; tt.y = tt.y * cf + a * ea4.y;
        tt.z = tt.z * cf + a * ea4.z; tt.w = tt.w * cf + a * ea4.w;
        m = nm;
    }

    float4 o = av;
#pragma unroll
    for (int s = 0; s < 8; ++s) {
        const int sl = h * 8 + s;
        const float t0 = __shfl_sync(0xffffffffu, tt.x, sl);
        const float t1 = __shfl_sync(0xffffffffu, tt.y, sl);
        const float t2 = __shfl_sync(0xffffffffu, tt.z, sl);
        const float t3 = __shfl_sync(0xffffffffu, tt.w, sl);
        const float* wr = we_sm + (s * 4) * 132 + d0;
        const float4 w0 = *reinterpret_cast<const float4*>(wr);
        const float4 w1 = *reinterpret_cast<const float4*>(wr + 132);
        const float4 w2 = *reinterpret_cast<const float4*>(wr + 264);
        const float4 w3 = *reinterpret_cast<const float4*>(wr + 396);
        o.x += t0 * w0.x + t1 * w1.x + t2 * w2.x + t3 * w3.x;
        o.y += t0 * w0.y + t1 * w1.y + t2 * w2.y + t3 * w3.y;
        o.z += t0 * w0.z + t1 * w1.z + t2 * w2.z + t3 * w3.z;
        o.w += t0 * w0.w + t1 * w1.w + t2 * w2.w + t3 * w3.w;
    }

    const float inv = (den > 0.f) ? 1.f / den : 0.f;
    const float4 sk4 = ldg_cs(g_sk + (size_t)n * 128 + d0);
    float4 r4;
    float vx = sk4.x + o.x * inv; r4.x = (vx > 0.f) ? vx : expm1f(vx);
    float vy = sk4.y + o.y * inv; r4.y = (vy > 0.f) ? vy : expm1f(vy);
    float vz = sk4.z + o.z * inv; r4.z = (vz > 0.f) ? vz : expm1f(vz);
    float vw = sk4.w + o.w * inv; r4.w = (vw > 0.f) ? vw : expm1f(vw);
    __stcs(reinterpret_cast<float4*>(outp + (size_t)n * 128 + d0), r4);
}

// ---------------- pooling + classifier -------------------------------------
__global__ __launch_bounds__(128) void bounds_kernel(const int* __restrict__ batch) {
    int b = threadIdx.x;
    if (b <= BB) {
        int lo = 0, hi = NN;
        while (lo < hi) {
            int mid = (lo + hi) >> 1;
            if (batch[mid] < b) lo = mid + 1; else hi = mid;
        }
        g_bnd[b] = lo;
    }
    for (int i = threadIdx.x; i < BB * HC; i += 128) g_pool[i] = 0.f;
}

// one block per (graph, quarter): branch-free unrolled accumulation
__global__ __launch_bounds__(128) void pool_kernel(const float* __restrict__ h)
{
    const int c  = threadIdx.x;
    const int b  = blockIdx.x >> 2;
    const int qu = blockIdx.x & 3;
    const int lo = g_bnd[b], hi = g_bnd[b + 1];
    const int span = hi - lo;
    const int r0 = lo + ((span * qu) >> 2);
    const int r1 = lo + ((span * (qu + 1)) >> 2);

    float a0 = 0.f, a1 = 0.f, a2 = 0.f, a3 = 0.f;
    int r = r0;
    for (; r + 4 <= r1; r += 4) {
        a0 += __ldcs(h + (size_t)(r + 0) * 128 + c);
        a1 += __ldcs(h + (size_t)(r + 1) * 128 + c);
        a2 += __ldcs(h + (size_t)(r + 2) * 128 + c);
        a3 += __ldcs(h + (size_t)(r + 3) * 128 + c);
    }
    for (; r < r1; ++r) a0 += __ldcs(h + (size_t)r * 128 + c);
    const float s = (a0 + a1) + (a2 + a3);
    if (r1 > r0) atomicAdd(&g_pool[b * 128 + c], s);
}

__global__ __launch_bounds__(1024) void classifier_kernel(const float* __restrict__ wlin,
                                                          const float* __restrict__ blin,
                                                          float* __restrict__ out)
{
    const int t = threadIdx.x;
    const int b = t >> 4, o = t & 15;
    int cnt = g_bnd[b + 1] - g_bnd[b];
    float invc = 1.f / (float)(cnt > 0 ? cnt : 1);
    float dot = 0.f;
    for (int c = 0; c < 128; ++c) dot = fmaf(g_pool[b * 128 + c], wlin[c * 16 + o], dot);
    float s = dot * invc + blin[o];
    float mx = s;
#pragma unroll
    for (int off = 8; off > 0; off >>= 1) mx = fmaxf(mx, __shfl_xor_sync(0xffffffffu, mx, off));
    float ex = __expf(s - mx);
    float sm = ex;
#pragma unroll
    for (int off = 8; off > 0; off >>= 1) sm += __shfl_xor_sync(0xffffffffu, sm, off);
    out[b * 16 + o] = (s - mx) - logf(sm);
}

// ---------------- launch ----------------------------------------------------
extern "C" void kernel_launch(void* const* d_in, const int* in_sizes, int n_in,
                              void* d_out, int out_size)
{
    const float* x     = (const float*)d_in[0];
    const int*   ei    = (const int*)d_in[1];
    const float* ea    = (const float*)d_in[2];
    const int*   batch = (const int*)d_in[3];
    const float* wq1 = (const float*)d_in[4];  const float* bq1 = (const float*)d_in[5];
    const float* wk1 = (const float*)d_in[6];  const float* bk1 = (const float*)d_in[7];
    const float* wv1 = (const float*)d_in[8];  const float* bv1 = (const float*)d_in[9];
    const float* we1 = (const float*)d_in[10];
    const float* ws1 = (const float*)d_in[11]; const float* bs1 = (const float*)d_in[12];
    const float* wq2 = (const float*)d_in[13]; const float* bq2 = (const float*)d_in[14];
    const float* wk2 = (const float*)d_in[15]; const float* bk2 = (const float*)d_in[16];
    const float* wv2 = (const float*)d_in[17]; const float* bv2 = (const float*)d_in[18];
    const float* we2 = (const float*)d_in[19];
    const float* ws2 = (const float*)d_in[20]; const float* bs2 = (const float*)d_in[21];
    const float* wlin = (const float*)d_in[22];
    const float* blin = (const float*)d_in[23];

    const int* src = ei;
    const int* tgt = ei + EE;

    float *qn, *sk, *U, *h1, *h2, *zb;
    void *knb, *vnb;
    cudaGetSymbolAddress((void**)&qn, g_qn);
    cudaGetSymbolAddress(&knb, g_knb);
    cudaGetSymbolAddress(&vnb, g_vnb);
    cudaGetSymbolAddress((void**)&sk, g_sk);
    cudaGetSymbolAddress((void**)&U,  g_U);
    cudaGetSymbolAddress((void**)&h1, g_h1);
    cudaGetSymbolAddress((void**)&h2, g_h2);
    cudaGetSymbolAddress((void**)&zb, g_zero);

    cudaFuncSetAttribute(node_gemm_mma, cudaFuncAttributeMaxDynamicSharedMemorySize, SMTOT);

    // 1: weight pre-split + zero deg
    WArgs wa;
    wa.w[0] = wq1; wa.w[1] = wk1; wa.w[2] = wv1; wa.w[3] = ws1;
    wa.w[4] = wq2; wa.w[5] = wk2; wa.w[6] = wv2; wa.w[7] = ws2;
    wa.w[8] = we1; wa.w[9] = we2;
    setup_kernel<<<dim3(64, 10), 256>>>(wa);

    // 2-3: histogram + scan phase 1
    hist_kernel<<<(EE + 255) / 256, 256>>>(tgt);
    scan1_kernel<<<NB, 256>>>();

    // 4: layer-1 GEMM (persistent CTAs; profiled slot #4)
    G5 a1;
    a1.bias[0] = bq1; a1.bias[1] = bk1; a1.bias[2] = bv1; a1.bias[3] = bs1; a1.bias[4] = zb;
    a1.out[0] = qn; a1.out[1] = knb; a1.out[2] = vnb; a1.out[3] = sk; a1.out[4] = U;
    a1.wbase = 0;
    node_gemm_mma<<<152, 512, SMTOT>>>(x, a1, NN);

    // 5-7: finish CSR
    scan2_kernel<<<1, 256>>>();
    scan3_kernel<<<NB, 256>>>();
    scatter_kernel<<<(EE + 255) / 256, 256>>>(src, tgt);

    // 8: layer-1 edge attention
    edge_attn<<<(NN + 7) / 8, 256>>>(ea, we1, h1);

    // 9-10: layer 2
    G5 a2;
    a2.bias[0] = bq2; a2.bias[1] = bk2; a2.bias[2] = bv2; a2.bias[3] = bs2; a2.bias[4] = zb;
    a2.out[0] = qn; a2.out[1] = knb; a2.out[2] = vnb; a2.out[3] = sk; a2.out[4] = U;
    a2.wbase = 4;
    node_gemm_mma<<<152, 512, SMTOT>>>(h1, a2, NN);
    edge_attn<<<(NN + 7) / 8, 256>>>(ea, we2, h2);

    // 11-13: pool + classify
    bounds_kernel<<<1, 128>>>(batch);
    pool_kernel<<<BB * 4, 128>>>(h2);
    classifier_kernel<<<1, 1024>>>(wlin, blin, (float*)d_out);
}

// round 17
// speedup vs baseline: 1.3577x; 1.3577x over previous
#include <cuda_runtime.h>
#include <cuda_bf16.h>
#include <math.h>
#include <stdint.h>

#define NN 50000
#define EE 800000
#define HC 128
#define BB 64
#define OUTC 16
#define NB 196   // (NN+255)/256

// ---------------- scratch (device globals; no allocation allowed) ----------
__device__ float g_qn[NN * HC];
__device__ __nv_bfloat16 g_knb[NN * HC];
__device__ __nv_bfloat16 g_vnb[NN * HC];
__device__ float g_sk[NN * HC];
__device__ float g_U [NN * HC];
__device__ float g_h1[NN * HC];
__device__ float g_h2[NN * HC];
__device__ int   g_deg[NN];
__device__ int   g_off[NN + 1];
__device__ int   g_cur[NN];
__device__ int   g_bsum[NB];
__device__ int   g_boff[NB];
__device__ int   g_psrc[EE];
__device__ int   g_peid[EE];
__device__ float g_pool[BB * HC];
__device__ int   g_bnd[BB + 1];
__device__ float g_zero[128];    // stays zero (zero-initialized, never written)
// pre-split transposed weights: [10 matrices][n(128)][k(128)] bf16 hi/lo
// m 0..3: layer1 q/k/v/s, 4..7: layer2, 8: Bu(we1), 9: Bu(we2)
__device__ __nv_bfloat16 g_wth[10 * 128 * 128];
__device__ __nv_bfloat16 g_wtl[10 * 128 * 128];

// ---------------- helpers ----------------------------------------------------
__device__ __forceinline__ uint32_t smem_u32(const void* p) {
    uint32_t a;
    asm("{ .reg .u64 t; cvta.to.shared.u64 t, %1; cvt.u32.u64 %0, t; }" : "=r"(a) : "l"(p));
    return a;
}
__device__ __forceinline__ void ldsm4(uint32_t* r, uint32_t addr) {
    asm volatile("ldmatrix.sync.aligned.m8n8.x4.shared.b16 {%0,%1,%2,%3}, [%4];"
        : "=r"(r[0]), "=r"(r[1]), "=r"(r[2]), "=r"(r[3]) : "r"(addr));
}
__device__ __forceinline__ void mma_bf16(float* d, const uint32_t* a, const uint32_t* b) {
    asm volatile(
        "mma.sync.aligned.m16n8k16.row.col.f32.bf16.bf16.f32 "
        "{%0,%1,%2,%3}, {%4,%5,%6,%7}, {%8,%9}, {%0,%1,%2,%3};"
        : "+f"(d[0]), "+f"(d[1]), "+f"(d[2]), "+f"(d[3])
        : "r"(a[0]), "r"(a[1]), "r"(a[2]), "r"(a[3]), "r"(b[0]), "r"(b[1]));
}
// streaming 128-bit load: LDG.E.CS.128
__device__ __forceinline__ float4 ldg_cs(const float* p) {
    return __ldcs(reinterpret_cast<const float4*>(p));
}
// bf16x4 gather -> fp32 (kn/vn)
__device__ __forceinline__ float4 ldg_bf4(const __nv_bfloat16* p) {
    const uint2 r = __ldg(reinterpret_cast<const uint2*>(p));
    const __nv_bfloat162 b0 = *reinterpret_cast<const __nv_bfloat162*>(&r.x);
    const __nv_bfloat162 b1 = *reinterpret_cast<const __nv_bfloat162*>(&r.y);
    const float2 f0 = __bfloat1622float2(b0);
    const float2 f1 = __bfloat1622float2(b1);
    return make_float4(f0.x, f0.y, f1.x, f1.y);
}

// ---------------- setup: weight split/transpose + zero deg ------------------
struct WArgs { const float* w[10]; };

__global__ void setup_kernel(WArgs a) {
    const int m = blockIdx.y;
    const float* __restrict__ W = a.w[m];
    int i = blockIdx.x * 256 + threadIdx.x;   // 0..16383
    int n = i >> 7, k = i & 127;
    float v;
    if (m < 8) {
        v = W[k * 128 + n];                   // transpose of [128,128]
    } else {
        // Bu[k][n] for we [32,128]: block-diagonal per head
        v = ((n >> 5) == (k >> 5)) ? W[(n & 31) * 128 + k] : 0.f;
    }
    __nv_bfloat16 hi = __float2bfloat16(v);
    float lof = v - __bfloat162float(hi);
    g_wth[m * 16384 + n * 128 + k] = hi;
    g_wtl[m * 16384 + n * 128 + k] = __float2bfloat16(lof);

    // fused zeroing (linear gid over the full 640-block grid)
    int gid = (blockIdx.y * 64 + blockIdx.x) * 256 + threadIdx.x;
    if (gid < NN) g_deg[gid] = 0;
}

__global__ void hist_kernel(const int* __restrict__ tgt) {
    int e = blockIdx.x * 256 + threadIdx.x;
    if (e < EE) atomicAdd(&g_deg[tgt[e]], 1);
}

// phase 1: per-block local exclusive scan + block totals
__global__ __launch_bounds__(256) void scan1_kernel() {
    __shared__ int sh[256];
    const int t = threadIdx.x;
    const int i = blockIdx.x * 256 + t;
    int v = (i < NN) ? g_deg[i] : 0;
    sh[t] = v;
    __syncthreads();
#pragma unroll
    for (int off = 1; off < 256; off <<= 1) {
        int x = (t >= off) ? sh[t - off] : 0;
        __syncthreads();
        sh[t] += x;
        __syncthreads();
    }
    if (i < NN) g_off[i] = sh[t] - v;     // local exclusive
    if (t == 255) g_bsum[blockIdx.x] = sh[255];
}

// phase 2: scan of block totals (single small block)
__global__ __launch_bounds__(256) void scan2_kernel() {
    __shared__ int sh[256];
    const int t = threadIdx.x;
    int v = (t < NB) ? g_bsum[t] : 0;
    sh[t] = v;
    __syncthreads();
#pragma unroll
    for (int off = 1; off < 256; off <<= 1) {
        int x = (t >= off) ? sh[t - off] : 0;
        __syncthreads();
        sh[t] += x;
        __syncthreads();
    }
    if (t < NB) g_boff[t] = sh[t] - v;    // exclusive
    if (t == NB - 1) g_off[NN] = sh[t];
}

// phase 3: add block offsets, init cursors
__global__ __launch_bounds__(256) void scan3_kernel() {
    const int i = blockIdx.x * 256 + threadIdx.x;
    if (i < NN) {
        int o = g_off[i] + g_boff[i >> 8];
        g_off[i] = o;
        g_cur[i] = o;
    }
}

__global__ void scatter_kernel(const int* __restrict__ src, const int* __restrict__ tgt) {
    int e = blockIdx.x * 256 + threadIdx.x;
    if (e < EE) {
        int p = atomicAdd(&g_cur[tgt[e]], 1);
        g_psrc[p] = src[e];
        g_peid[p] = e;
    }
}

// ---------------- HMMA node GEMM + fused U pass ------------------------------
// 512 threads, 4x4 warp tiling, one 128-row tile per CTA (grid=391).
// z=0: qn fp32 + smem hi/lo cache; z=1: kn bf16 (2-term); z=2: vn bf16 (2-term);
// z=3: sk fp32; z=4: U = qn @ Bu (block-diagonal, 2 ksteps/warp).
struct G5 {
    const float* bias[5];
    void*        out[5];
    int          wbase;   // 0 for layer1, 4 for layer2
};

#define ROWB   272
#define OFF_AH 0
#define OFF_AL (128 * ROWB)
#define OFF_BH (2 * 128 * ROWB)
#define OFF_BL (3 * 128 * ROWB)
#define OFF_QH (4 * 128 * ROWB)
#define OFF_QL (5 * 128 * ROWB)
#define SMTOT  (6 * 128 * ROWB)

__global__ __launch_bounds__(512, 1) void node_gemm_mma(const float* __restrict__ A, G5 g, int M)
{
    extern __shared__ char sm[];
    const uint32_t sb = smem_u32(sm);
    const int tid  = threadIdx.x;
    const int wid  = tid >> 5;
    const int lane = tid & 31;
    const int wid_n = wid & 3;     // 32-col strip
    const int wid_m = wid >> 2;    // 32-row strip
    const int m0   = blockIdx.x * 128;

    // --- convert A tile (128x128 fp32) to bf16 hi/lo in padded smem ---
    for (int idx = tid; idx < 128 * 32; idx += 512) {
        int r  = idx >> 5;
        int kc = (idx & 31) * 4;
        int grow = m0 + r;
        float4 v = make_float4(0.f, 0.f, 0.f, 0.f);
        if (grow < M) v = *reinterpret_cast<const float4*>(A + (size_t)grow * 128 + kc);
        __nv_bfloat16 h0 = __float2bfloat16(v.x), h1 = __float2bfloat16(v.y);
        __nv_bfloat16 h2 = __float2bfloat16(v.z), h3 = __float2bfloat16(v.w);
        __nv_bfloat16 l0 = __float2bfloat16(v.x - __bfloat162float(h0));
        __nv_bfloat16 l1 = __float2bfloat16(v.y - __bfloat162float(h1));
        __nv_bfloat16 l2 = __float2bfloat16(v.z - __bfloat162float(h2));
        __nv_bfloat16 l3 = __float2bfloat16(v.w - __bfloat162float(h3));
        ushort4 hp = make_ushort4(__bfloat16_as_ushort(h0), __bfloat16_as_ushort(h1),
                                  __bfloat16_as_ushort(h2), __bfloat16_as_ushort(h3));
        ushort4 lp = make_ushort4(__bfloat16_as_ushort(l0), __bfloat16_as_ushort(l1),
                                  __bfloat16_as_ushort(l2), __bfloat16_as_ushort(l3));
        *reinterpret_cast<ushort4*>(sm + OFF_AH + r * ROWB + kc * 2) = hp;
        *reinterpret_cast<ushort4*>(sm + OFF_AL + r * ROWB + kc * 2) = lp;
    }

    // fragment addresses
    const uint32_t a_base = sb + (uint32_t)((wid_m * 32 + (lane & 15)) * ROWB + (lane >> 4) * 16);
    const uint32_t b4_base = sb + (uint32_t)(((lane & 7) + ((lane >> 4) << 3)) * ROWB
                                             + (((lane >> 3) & 1) << 4));

    const int r0l = wid_m * 32 + (lane >> 2);   // local row of acc[0][.][0/1]
    const int cb  = (lane & 3) * 2;

    float acc[2][4][4];

    for (int z = 0; z < 5; ++z) {
        __syncthreads();   // previous B reads done; z=0 Aq writes visible for z=4
        const int wsel = (z < 4) ? (g.wbase + z) : (8 + (g.wbase >> 2));
        const __nv_bfloat16* shp = g_wth + (size_t)wsel * 16384;
        const __nv_bfloat16* slp = g_wtl + (size_t)wsel * 16384;
        for (int idx = tid; idx < 128 * 16; idx += 512) {
            int r = idx >> 4, s = idx & 15;
            *reinterpret_cast<uint4*>(sm + OFF_BH + r * ROWB + s * 16) =
                *reinterpret_cast<const uint4*>(shp + r * 128 + s * 8);
            *reinterpret_cast<uint4*>(sm + OFF_BL + r * ROWB + s * 16) =
                *reinterpret_cast<const uint4*>(slp + r * 128 + s * 8);
        }
        __syncthreads();

        const uint32_t ahof = (z == 4) ? OFF_QH : OFF_AH;
        const uint32_t alof = (z == 4) ? OFF_QL : OFF_AL;

#pragma unroll
        for (int mt = 0; mt < 2; ++mt)
#pragma unroll
            for (int nt = 0; nt < 4; ++nt)
#pragma unroll
                for (int q = 0; q < 4; ++q) acc[mt][nt][q] = 0.f;

        if (z == 1 || z == 2) {
            // 2-term split (output truncated to bf16 anyway): ah*bh + ah*bl
#pragma unroll 2
            for (int ki = 0; ki < 8; ++ki) {
                const uint32_t ko = (uint32_t)(ki * 32);
                uint32_t ah[2][4], bh[2][4], bl[2][4];
#pragma unroll
                for (int mt = 0; mt < 2; ++mt)
                    ldsm4(ah[mt], a_base + (uint32_t)(mt * 16 * ROWB) + OFF_AH + ko);
#pragma unroll
                for (int np = 0; np < 2; ++np) {
                    const uint32_t bo = (uint32_t)((wid_n * 32 + np * 16) * ROWB) + ko;
                    ldsm4(bh[np], b4_base + OFF_BH + bo);
                    ldsm4(bl[np], b4_base + OFF_BL + bo);
                }
#pragma unroll
                for (int mt = 0; mt < 2; ++mt)
#pragma unroll
                    for (int np = 0; np < 2; ++np) {
                        mma_bf16(acc[mt][np * 2],     ah[mt], bh[np]);
                        mma_bf16(acc[mt][np * 2],     ah[mt], bl[np]);
                        mma_bf16(acc[mt][np * 2 + 1], ah[mt], bh[np] + 2);
                        mma_bf16(acc[mt][np * 2 + 1], ah[mt], bl[np] + 2);
                    }
            }
        } else {
            const int ks0 = (z == 4) ? (wid_n * 2) : 0;
            const int ksN = (z == 4) ? 2 : 8;
#pragma unroll 2
            for (int ki = 0; ki < ksN; ++ki) {
                const uint32_t ko = (uint32_t)((ks0 + ki) * 32);
                uint32_t ah[2][4], al[2][4], bh[2][4], bl[2][4];
#pragma unroll
                for (int mt = 0; mt < 2; ++mt) {
                    ldsm4(ah[mt], a_base + (uint32_t)(mt * 16 * ROWB) + ahof + ko);
                    ldsm4(al[mt], a_base + (uint32_t)(mt * 16 * ROWB) + alof + ko);
                }
#pragma unroll
                for (int np = 0; np < 2; ++np) {
                    const uint32_t bo = (uint32_t)((wid_n * 32 + np * 16) * ROWB) + ko;
                    ldsm4(bh[np], b4_base + OFF_BH + bo);
                    ldsm4(bl[np], b4_base + OFF_BL + bo);
                }
#pragma unroll
                for (int mt = 0; mt < 2; ++mt)
#pragma unroll
                    for (int np = 0; np < 2; ++np) {
                        mma_bf16(acc[mt][np * 2],     ah[mt], bh[np]);
                        mma_bf16(acc[mt][np * 2],     ah[mt], bl[np]);
                        mma_bf16(acc[mt][np * 2],     al[mt], bh[np]);
                        mma_bf16(acc[mt][np * 2 + 1], ah[mt], bh[np] + 2);
                        mma_bf16(acc[mt][np * 2 + 1], ah[mt], bl[np] + 2);
                        mma_bf16(acc[mt][np * 2 + 1], al[mt], bh[np] + 2);
                    }
            }
        }

        // --- epilogue: bias add + store (z=1,2 -> bf16; else fp32; z=0 qn cache) ---
        const float* bias = g.bias[z];
        const bool is_bf = (z == 1 || z == 2);
        float* outf = (float*)g.out[z];
        __nv_bfloat16* outb = (__nv_bfloat16*)g.out[z];
#pragma unroll
        for (int mt = 0; mt < 2; ++mt) {
            const int rl0 = r0l + mt * 16;
            const int gr0 = m0 + rl0;
            const int gr1 = gr0 + 8;
#pragma unroll
            for (int nt = 0; nt < 4; ++nt) {
                const int c = wid_n * 32 + nt * 8 + cb;
                const float2 bv = *reinterpret_cast<const float2*>(bias + c);
                float2 o0 = make_float2(acc[mt][nt][0] + bv.x, acc[mt][nt][1] + bv.y);
                float2 o1 = make_float2(acc[mt][nt][2] + bv.x, acc[mt][nt][3] + bv.y);
                if (is_bf) {
                    if (gr0 < M)
                        *reinterpret_cast<__nv_bfloat162*>(outb + (size_t)gr0 * 128 + c) =
                            __floats2bfloat162_rn(o0.x, o0.y);
                    if (gr1 < M)
                        *reinterpret_cast<__nv_bfloat162*>(outb + (size_t)gr1 * 128 + c) =
                            __floats2bfloat162_rn(o1.x, o1.y);
                } else {
                    if (gr0 < M) *reinterpret_cast<float2*>(outf + (size_t)gr0 * 128 + c) = o0;
                    if (gr1 < M) *reinterpret_cast<float2*>(outf + (size_t)gr1 * 128 + c) = o1;
                }
                if (z == 0) {
                    __nv_bfloat16 h0 = __float2bfloat16(o0.x), h1 = __float2bfloat16(o0.y);
                    __nv_bfloat16 l0 = __float2bfloat16(o0.x - __bfloat162float(h0));
                    __nv_bfloat16 l1 = __float2bfloat16(o0.y - __bfloat162float(h1));
                    *reinterpret_cast<ushort2*>(sm + OFF_QH + rl0 * ROWB + c * 2) =
                        make_ushort2(__bfloat16_as_ushort(h0), __bfloat16_as_ushort(h1));
                    *reinterpret_cast<ushort2*>(sm + OFF_QL + rl0 * ROWB + c * 2) =
                        make_ushort2(__bfloat16_as_ushort(l0), __bfloat16_as_ushort(l1));
                    __nv_bfloat16 h2 = __float2bfloat16(o1.x), h3 = __float2bfloat16(o1.y);
                    __nv_bfloat16 l2 = __float2bfloat16(o1.x - __bfloat162float(h2));
                    __nv_bfloat16 l3 = __float2bfloat16(o1.y - __bfloat162float(h3));
                    *reinterpret_cast<ushort2*>(sm + OFF_QH + (rl0 + 8) * ROWB + c * 2) =
                        make_ushort2(__bfloat16_as_ushort(h2), __bfloat16_as_ushort(h3));
                    *reinterpret_cast<ushort2*>(sm + OFF_QL + (rl0 + 8) * ROWB + c * 2) =
                        make_ushort2(__bfloat16_as_ushort(l2), __bfloat16_as_ushort(l3));
                }
            }
        }
    }
}

// ---------------- fused edge attention: warp per target node -----------------
// lane layout: head h = lane>>3, dims d0 = (lane&7)*4 (float4 per lane)
// kn/vn in bf16 (half traffic); q/U/sk fp32; ea streamed .cs
__global__ __launch_bounds__(256) void edge_attn(const float* __restrict__ ea,
                                                 const float* __restrict__ we,
                                                 float* __restrict__ outp)
{
    __shared__ float we_sm[32 * 132];
    for (int i = threadIdx.x; i < 32 * 128; i += 256)
        we_sm[(i >> 7) * 132 + (i & 127)] = we[i];
    __syncthreads();

    const int lane = threadIdx.x & 31;
    const int n = blockIdx.x * 8 + (threadIdx.x >> 5);
    if (n >= NN) return;

    const int h   = lane >> 3;
    const int sub = lane & 7;
    const int d0  = h * 32 + sub * 4;

    const float4 q4 = ldg_cs(g_qn + (size_t)n * 128 + d0);
    const float4 u4 = ldg_cs(g_U  + (size_t)n * 128 + d0);
    float m = -1e30f, den = 0.f;
    float4 av = make_float4(0.f, 0.f, 0.f, 0.f);
    float4 tt = make_float4(0.f, 0.f, 0.f, 0.f);

    const int e0 = g_off[n], e1 = g_off[n + 1];
    const float RS = 0.17677669529663687f * 1.4426950408889634f;  // 1/sqrt(32) * log2(e)

    int e = e0;
    for (; e + 2 <= e1; e += 2) {
        const int sA = g_psrc[e],     sB = g_psrc[e + 1];
        const int iA = g_peid[e],     iB = g_peid[e + 1];
        const float4 eaA = ldg_cs(ea + (size_t)iA * 32 + sub * 4);
        const float4 eaB = ldg_cs(ea + (size_t)iB * 32 + sub * 4);
        const float4 kA  = ldg_bf4(g_knb + (size_t)sA * 128 + d0);
        const float4 kB  = ldg_bf4(g_knb + (size_t)sB * 128 + d0);
        const float4 vA  = ldg_bf4(g_vnb + (size_t)sA * 128 + d0);
        const float4 vB  = ldg_bf4(g_vnb + (size_t)sB * 128 + d0);

        float rA = q4.x * kA.x + q4.y * kA.y + q4.z * kA.z + q4.w * kA.w
                 + eaA.x * u4.x + eaA.y * u4.y + eaA.z * u4.z + eaA.w * u4.w;
        float rB = q4.x * kB.x + q4.y * kB.y + q4.z * kB.z + q4.w * kB.w
                 + eaB.x * u4.x + eaB.y * u4.y + eaB.z * u4.z + eaB.w * u4.w;
        rA += __shfl_xor_sync(0xffffffffu, rA, 1);
        rB += __shfl_xor_sync(0xffffffffu, rB, 1);
        rA += __shfl_xor_sync(0xffffffffu, rA, 2);
        rB += __shfl_xor_sync(0xffffffffu, rB, 2);
        rA += __shfl_xor_sync(0xffffffffu, rA, 4);
        rB += __shfl_xor_sync(0xffffffffu, rB, 4);

        {
            const float al = rA * RS;
            const float nm = fmaxf(m, al);
            const float cf = exp2f(m - nm);
            const float a  = exp2f(al - nm);
            den = den * cf + a;
            av.x = av.x * cf + a * vA.x;  av.y = av.y * cf + a * vA.y;
            av.z = av.z * cf + a * vA.z;  av.w = av.w * cf + a * vA.w;
            tt.x = tt.x * cf + a * eaA.x; tt.y = tt.y * cf + a * eaA.y;
            tt.z = tt.z * cf + a * eaA.z; tt.w = tt.w * cf + a * eaA.w;
            m = nm;
        }
        {
            const float al = rB * RS;
            const float nm = fmaxf(m, al);
            const float cf = exp2f(m - nm);
            const float a  = exp2f(al - nm);
            den = den * cf + a;
            av.x = av.x * cf + a * vB.x;  av.y = av.y * cf + a * vB.y;
            av.z = av.z * cf + a * vB.z;  av.w = av.w * cf + a * vB.w;
            tt.x = tt.x * cf + a * eaB.x; tt.y = tt.y * cf + a * eaB.y;
            tt.z = tt.z * cf + a * eaB.z; tt.w = tt.w * cf + a * eaB.w;
            m = nm;
        }
    }
    for (; e < e1; ++e) {
        const int src = g_psrc[e];
        const int eid = g_peid[e];
        const float4 ea4 = ldg_cs(ea + (size_t)eid * 32 + sub * 4);
        const float4 k4  = ldg_bf4(g_knb + (size_t)src * 128 + d0);
        float r = q4.x * k4.x + q4.y * k4.y + q4.z * k4.z + q4.w * k4.w
                + ea4.x * u4.x + ea4.y * u4.y + ea4.z * u4.z + ea4.w * u4.w;
        r += __shfl_xor_sync(0xffffffffu, r, 1);
        r += __shfl_xor_sync(0xffffffffu, r, 2);
        r += __shfl_xor_sync(0xffffffffu, r, 4);

        const float al = r * RS;
        const float nm = fmaxf(m, al);
        const float cf = exp2f(m - nm);
        const float a  = exp2f(al - nm);
        den = den * cf + a;
        const float4 v4 = ldg_bf4(g_vnb + (size_t)src * 128 + d0);
        av.x = av.x * cf + a * v4.x;  av.y = av.y * cf + a * v4.y;
        av.z = av.z * cf + a * v4.z;  av.w = av.w * cf + a * v4.w;
        tt.x = tt.x * cf + a * ea4.x; tt.y = tt.y * cf + a * ea4.y;
        tt.z = tt.z * cf + a * ea4.z; tt.w = tt.w * cf + a * ea4.w;
        m = nm;
    }

    float4 o = av;
#pragma unroll
    for (int s = 0; s < 8; ++s) {
        const int sl = h * 8 + s;
        const float t0 = __shfl_sync(0xffffffffu, tt.x, sl);
        const float t1 = __shfl_sync(0xffffffffu, tt.y, sl);
        const float t2 = __shfl_sync(0xffffffffu, tt.z, sl);
        const float t3 = __shfl_sync(0xffffffffu, tt.w, sl);
        const float* wr = we_sm + (s * 4) * 132 + d0;
        const float4 w0 = *reinterpret_cast<const float4*>(wr);
        const float4 w1 = *reinterpret_cast<const float4*>(wr + 132);
        const float4 w2 = *reinterpret_cast<const float4*>(wr + 264);
        const float4 w3 = *reinterpret_cast<const float4*>(wr + 396);
        o.x += t0 * w0.x + t1 * w1.x + t2 * w2.x + t3 * w3.x;
        o.y += t0 * w0.y + t1 * w1.y + t2 * w2.y + t3 * w3.y;
        o.z += t0 * w0.z + t1 * w1.z + t2 * w2.z + t3 * w3.z;
        o.w += t0 * w0.w + t1 * w1.w + t2 * w2.w + t3 * w3.w;
    }

    const float inv = (den > 0.f) ? 1.f / den : 0.f;
    const float4 sk4 = ldg_cs(g_sk + (size_t)n * 128 + d0);
    float4 r4;
    float vx = sk4.x + o.x * inv; r4.x = (vx > 0.f) ? vx : expm1f(vx);
    float vy = sk4.y + o.y * inv; r4.y = (vy > 0.f) ? vy : expm1f(vy);
    float vz = sk4.z + o.z * inv; r4.z = (vz > 0.f) ? vz : expm1f(vz);
    float vw = sk4.w + o.w * inv; r4.w = (vw > 0.f) ? vw : expm1f(vw);
    __stcs(reinterpret_cast<float4*>(outp + (size_t)n * 128 + d0), r4);
}

// ---------------- pooling + classifier -------------------------------------
__global__ __launch_bounds__(128) void bounds_kernel(const int* __restrict__ batch) {
    int b = threadIdx.x;
    if (b <= BB) {
        int lo = 0, hi = NN;
        while (lo < hi) {
            int mid = (lo + hi) >> 1;
            if (batch[mid] < b) lo = mid + 1; else hi = mid;
        }
        g_bnd[b] = lo;
    }
    for (int i = threadIdx.x; i < BB * HC; i += 128) g_pool[i] = 0.f;
}

// one block per (graph, quarter): branch-free unrolled accumulation
__global__ __launch_bounds__(128) void pool_kernel(const float* __restrict__ h)
{
    const int c  = threadIdx.x;
    const int b  = blockIdx.x >> 2;
    const int qu = blockIdx.x & 3;
    const int lo = g_bnd[b], hi = g_bnd[b + 1];
    const int span = hi - lo;
    const int r0 = lo + ((span * qu) >> 2);
    const int r1 = lo + ((span * (qu + 1)) >> 2);

    float a0 = 0.f, a1 = 0.f, a2 = 0.f, a3 = 0.f;
    int r = r0;
    for (; r + 4 <= r1; r += 4) {
        a0 += __ldcs(h + (size_t)(r + 0) * 128 + c);
        a1 += __ldcs(h + (size_t)(r + 1) * 128 + c);
        a2 += __ldcs(h + (size_t)(r + 2) * 128 + c);
        a3 += __ldcs(h + (size_t)(r + 3) * 128 + c);
    }
    for (; r < r1; ++r) a0 += __ldcs(h + (size_t)r * 128 + c);
    const float s = (a0 + a1) + (a2 + a3);
    if (r1 > r0) atomicAdd(&g_pool[b * 128 + c], s);
}

__global__ __launch_bounds__(1024) void classifier_kernel(const float* __restrict__ wlin,
                                                          const float* __restrict__ blin,
                                                          float* __restrict__ out)
{
    const int t = threadIdx.x;
    const int b = t >> 4, o = t & 15;
    int cnt = g_bnd[b + 1] - g_bnd[b];
    float invc = 1.f / (float)(cnt > 0 ? cnt : 1);
    float dot = 0.f;
    for (int c = 0; c < 128; ++c) dot = fmaf(g_pool[b * 128 + c], wlin[c * 16 + o], dot);
    float s = dot * invc + blin[o];
    float mx = s;
#pragma unroll
    for (int off = 8; off > 0; off >>= 1) mx = fmaxf(mx, __shfl_xor_sync(0xffffffffu, mx, off));
    float ex = __expf(s - mx);
    float sm = ex;
#pragma unroll
    for (int off = 8; off > 0; off >>= 1) sm += __shfl_xor_sync(0xffffffffu, sm, off);
    out[b * 16 + o] = (s - mx) - logf(sm);
}

// ---------------- launch ----------------------------------------------------
extern "C" void kernel_launch(void* const* d_in, const int* in_sizes, int n_in,
                              void* d_out, int out_size)
{
    const float* x     = (const float*)d_in[0];
    const int*   ei    = (const int*)d_in[1];
    const float* ea    = (const float*)d_in[2];
    const int*   batch = (const int*)d_in[3];
    const float* wq1 = (const float*)d_in[4];  const float* bq1 = (const float*)d_in[5];
    const float* wk1 = (const float*)d_in[6];  const float* bk1 = (const float*)d_in[7];
    const float* wv1 = (const float*)d_in[8];  const float* bv1 = (const float*)d_in[9];
    const float* we1 = (const float*)d_in[10];
    const float* ws1 = (const float*)d_in[11]; const float* bs1 = (const float*)d_in[12];
    const float* wq2 = (const float*)d_in[13]; const float* bq2 = (const float*)d_in[14];
    const float* wk2 = (const float*)d_in[15]; const float* bk2 = (const float*)d_in[16];
    const float* wv2 = (const float*)d_in[17]; const float* bv2 = (const float*)d_in[18];
    const float* we2 = (const float*)d_in[19];
    const float* ws2 = (const float*)d_in[20]; const float* bs2 = (const float*)d_in[21];
    const float* wlin = (const float*)d_in[22];
    const float* blin = (const float*)d_in[23];

    const int* src = ei;
    const int* tgt = ei + EE;

    float *qn, *sk, *U, *h1, *h2, *zb;
    void *knb, *vnb;
    cudaGetSymbolAddress((void**)&qn, g_qn);
    cudaGetSymbolAddress(&knb, g_knb);
    cudaGetSymbolAddress(&vnb, g_vnb);
    cudaGetSymbolAddress((void**)&sk, g_sk);
    cudaGetSymbolAddress((void**)&U,  g_U);
    cudaGetSymbolAddress((void**)&h1, g_h1);
    cudaGetSymbolAddress((void**)&h2, g_h2);
    cudaGetSymbolAddress((void**)&zb, g_zero);

    cudaFuncSetAttribute(node_gemm_mma, cudaFuncAttributeMaxDynamicSharedMemorySize, SMTOT);

    // 1: weight pre-split + zero deg
    WArgs wa;
    wa.w[0] = wq1; wa.w[1] = wk1; wa.w[2] = wv1; wa.w[3] = ws1;
    wa.w[4] = wq2; wa.w[5] = wk2; wa.w[6] = wv2; wa.w[7] = ws2;
    wa.w[8] = we1; wa.w[9] = we2;
    setup_kernel<<<dim3(64, 10), 256>>>(wa);

    // 2-3: histogram + scan phase 1
    hist_kernel<<<(EE + 255) / 256, 256>>>(tgt);
    scan1_kernel<<<NB, 256>>>();

    const int gemm_grid = (NN + 127) / 128;

    // 4: layer-1 GEMM (one tile per CTA; profiled slot #4)
    G5 a1;
    a1.bias[0] = bq1; a1.bias[1] = bk1; a1.bias[2] = bv1; a1.bias[3] = bs1; a1.bias[4] = zb;
    a1.out[0] = qn; a1.out[1] = knb; a1.out[2] = vnb; a1.out[3] = sk; a1.out[4] = U;
    a1.wbase = 0;
    node_gemm_mma<<<gemm_grid, 512, SMTOT>>>(x, a1, NN);

    // 5-7: finish CSR
    scan2_kernel<<<1, 256>>>();
    scan3_kernel<<<NB, 256>>>();
    scatter_kernel<<<(EE + 255) / 256, 256>>>(src, tgt);

    // 8: layer-1 edge attention
    edge_attn<<<(NN + 7) / 8, 256>>>(ea, we1, h1);

    // 9-10: layer 2
    G5 a2;
    a2.bias[0] = bq2; a2.bias[1] = bk2; a2.bias[2] = bv2; a2.bias[3] = bs2; a2.bias[4] = zb;
    a2.out[0] = qn; a2.out[1] = knb; a2.out[2] = vnb; a2.out[3] = sk; a2.out[4] = U;
    a2.wbase = 4;
    node_gemm_mma<<<gemm_grid, 512, SMTOT>>>(h1, a2, NN);
    edge_attn<<<(NN + 7) / 8, 256>>>(ea, we2, h2);

    // 11-13: pool + classify
    bounds_kernel<<<1, 128>>>(batch);
    pool_kernel<<<BB * 4, 128>>>(h2);
    classifier_kernel<<<1, 1024>>>(wlin, blin, (float*)d_out);
}